// round 11
// baseline (speedup 1.0000x reference)
#include <cuda_runtime.h>
#include <cstdint>
#include <cstddef>

// f = H @ x + damp * x per molecule.
// hess: [M*96, 96] f32 row-major, ns: flat [M*96] f32, out: flat [M*96] f32.
// Final converged config (session-best R9): 456 persistent CTAs (3/SM), 2-stage
// TMA ring, per-warp third-tile mbarriers (12KB granularity), L2 evict_first,
// LDS.128 rotated-column consumer. Pinned at the measured ~6.4TB/s LTS ceiling:
// 308MB compulsory traffic / 6.4TB/s = 48.1us floor vs ~48.7us kernel time.
#define D 96
#define D4 24                      // D/4 vec4 columns
#define DD (D * D)
#define ROWS_W 32                  // rows per warp-tile
#define HW_BYTES (ROWS_W * D * 4)  // 12288 per warp third
#define H_BYTES  (DD * 4)          // 36864
#define X_BYTES  (D * 4)           // 384
#define NBLOCKS  456               // 152 SMs * 3 CTAs/SM

// dynamic smem layout:
//   [0, 2*H_BYTES)     : H stages (2 x 36864), thirds contiguous
//   [+, 2*3*X_BYTES)   : x copies [stage][warp]
//   [+, 6*8)           : mbarriers [stage][warp]
#define SMEM_X_OFF    (2 * H_BYTES)
#define SMEM_MBAR_OFF (SMEM_X_OFF + 6 * X_BYTES)
#define SMEM_TOTAL    (SMEM_MBAR_OFF + 6 * 8)

__device__ __constant__ float kDampF = (float)(0.1 * 627.5094740631 /
                                               (0.529177210903 * 0.529177210903));

__device__ __forceinline__ uint32_t s2u(const void* p) {
    uint32_t a;
    asm("{ .reg .u64 t; cvta.to.shared.u64 t, %1; cvt.u32.u64 %0, t; }"
        : "=r"(a) : "l"(p));
    return a;
}

__device__ __forceinline__ void mbar_init(uint32_t mbar, uint32_t count) {
    asm volatile("mbarrier.init.shared.b64 [%0], %1;" :: "r"(mbar), "r"(count) : "memory");
}

__device__ __forceinline__ void mbar_expect_tx(uint32_t mbar, uint32_t bytes) {
    asm volatile("mbarrier.arrive.expect_tx.shared.b64 _, [%0], %1;"
                 :: "r"(mbar), "r"(bytes) : "memory");
}

__device__ __forceinline__ void mbar_wait(uint32_t mbar, uint32_t parity) {
    asm volatile(
        "{\n\t"
        ".reg .pred P;\n\t"
        "WAIT_%=:\n\t"
        "mbarrier.try_wait.parity.shared.b64 P, [%0], %1;\n\t"
        "@!P bra WAIT_%=;\n\t"
        "}"
        :: "r"(mbar), "r"(parity) : "memory");
}

__device__ __forceinline__ void bulk_g2s_ef(uint32_t dst_smem, const void* src_gmem,
                                            uint32_t bytes, uint32_t mbar) {
    asm volatile(
        "{\n\t"
        ".reg .b64 pol;\n\t"
        "createpolicy.fractional.L2::evict_first.b64 pol, 1.0;\n\t"
        "cp.async.bulk.shared::cluster.global.mbarrier::complete_tx::bytes.L2::cache_hint "
        "[%0], [%1], %2, [%3], pol;\n\t"
        "}"
        :: "r"(dst_smem), "l"(src_gmem), "r"(bytes), "r"(mbar) : "memory");
}

extern __shared__ char smem_raw[];

// issue the three per-warp fetches of stage st for molecule base pointers hp/xp
__device__ __forceinline__ void issue_stage(uint32_t Hs_u, uint32_t xs_u, uint32_t mbar_base,
                                            int st, const float* hp, const float* xp) {
    const uint32_t hdst = Hs_u + (uint32_t)st * H_BYTES;
    const uint32_t xdst = xs_u + (uint32_t)(st * 3) * X_BYTES;
    const uint32_t mb   = mbar_base + (uint32_t)(st * 3) * 8u;
    #pragma unroll
    for (int w = 0; w < 3; ++w) {
        mbar_expect_tx(mb + 8u * w, HW_BYTES + X_BYTES);
        bulk_g2s_ef(hdst + (uint32_t)w * HW_BYTES, hp + w * (ROWS_W * D), HW_BYTES, mb + 8u * w);
        bulk_g2s_ef(xdst + (uint32_t)w * X_BYTES, xp, X_BYTES, mb + 8u * w);
    }
}

__global__ void __launch_bounds__(D, 3)
force_agg_kernel(const float* __restrict__ ns,
                 const float* __restrict__ hess,
                 float* __restrict__ out, int M) {
    float* Hs = reinterpret_cast<float*>(smem_raw);                 // [2][DD]
    float* xs = reinterpret_cast<float*>(smem_raw + SMEM_X_OFF);    // [2][3][D]
    const uint32_t mbar_base = s2u(smem_raw + SMEM_MBAR_OFF);       // [2][3]

    const int t = threadIdx.x;     // 0..95
    const int b = blockIdx.x;
    const int w = t >> 5;          // my warp = my third

    if (t < 6) mbar_init(mbar_base + 8u * t, 1);
    __syncthreads();

    // interleaved assignment (best measured config): molecules b, b+456, ...
    const int stride = gridDim.x;
    const int cnt = (M - b + stride - 1) / stride;

    const uint32_t Hs_u = s2u(Hs);
    const uint32_t xs_u = s2u(xs);

    const size_t mstepH = (size_t)stride * DD;
    const size_t mstepX = (size_t)stride * D;
    const float* hess_p = hess + (size_t)b * DD;
    const float* ns_p   = ns   + (size_t)b * D;
    float* out_p        = out  + (size_t)b * D + t;

    // prologue: stage 0 for k=0
    if (t == 0) issue_stage(Hs_u, xs_u, mbar_base, 0, hess_p, ns_p);
    const float* hess_next = hess_p + mstepH;
    const float* ns_next   = ns_p   + mstepX;

    const int c0 = t % D4;         // rotated vec4-column start (conflict-free)
    const uint32_t my_mb_off = (uint32_t)w * 8u;

    for (int k = 0; k < cnt; ++k) {
        const int s = k & 1;

        // prefetch k+1 into stage s^1 (freed by the sync ending iter k-1)
        if (t == 0 && (k + 1) < cnt)
            issue_stage(Hs_u, xs_u, mbar_base, s ^ 1, hess_next, ns_next);
        hess_next += mstepH;
        ns_next   += mstepX;

        // wait only for my warp's third of stage s (parity flips every stage reuse)
        mbar_wait(mbar_base + (uint32_t)(s * 3) * 8u + my_mb_off, (uint32_t)((k >> 1) & 1));

        // vectorized dot product: LDS.128 on H row and my warp's x copy
        const float4* __restrict__ Hrow4 =
            reinterpret_cast<const float4*>(Hs + (size_t)s * DD + (size_t)t * D);
        const float* __restrict__ xvec = xs + (s * 3 + w) * D;
        const float4* __restrict__ xv4 = reinterpret_cast<const float4*>(xvec);

        float a0 = 0.f, a1 = 0.f, a2 = 0.f, a3 = 0.f;
        int c = c0;
        #pragma unroll
        for (int it = 0; it < D4; ++it) {
            float4 h = Hrow4[c];
            float4 xv = xv4[c];
            a0 = fmaf(h.x, xv.x, a0);
            a1 = fmaf(h.y, xv.y, a1);
            a2 = fmaf(h.z, xv.z, a2);
            a3 = fmaf(h.w, xv.w, a3);
            ++c;
            if (c == D4) c = 0;
        }
        const float acc = fmaf(kDampF, xvec[t], (a0 + a1) + (a2 + a3));

        *out_p = acc;
        out_p += mstepX;

        // stage s fully consumed before iter k+1 refills it
        __syncthreads();
    }
}

extern "C" void kernel_launch(void* const* d_in, const int* in_sizes, int n_in,
                              void* d_out, int out_size) {
    const float* ns   = (const float*)d_in[0];   // [N_tot,3] -> flat [M*96]
    const float* hess = (const float*)d_in[1];   // [M*96, 96]
    float* out = (float*)d_out;

    const int M = in_sizes[1] / DD;              // 8192

    cudaFuncSetAttribute(force_agg_kernel,
                         cudaFuncAttributeMaxDynamicSharedMemorySize, SMEM_TOTAL);
    force_agg_kernel<<<NBLOCKS, D, SMEM_TOTAL>>>(ns, hess, out, M);
}

// round 12
// speedup vs baseline: 1.0186x; 1.0186x over previous
#include <cuda_runtime.h>
#include <cstdint>
#include <cstddef>

// f = H @ x + damp * x per molecule.
// hess: [M*96, 96] f32 row-major, ns: flat [M*96] f32, out: flat [M*96] f32.
// 456 persistent CTAs (3/SM), 2-stage TMA ring, per-warp H-third barriers,
// SINGLE x copy per stage (on warp0's barrier), L2 evict_first, LDS.128 consumer.
#define D 96
#define D4 24                      // D/4 vec4 columns
#define DD (D * D)
#define ROWS_W 32                  // rows per warp-tile
#define HW_BYTES (ROWS_W * D * 4)  // 12288 per warp third
#define H_BYTES  (DD * 4)          // 36864
#define X_BYTES  (D * 4)           // 384
#define NBLOCKS  456               // 152 SMs * 3 CTAs/SM

// dynamic smem layout:
//   [0, 2*H_BYTES)     : H stages (2 x 36864), thirds contiguous
//   [+, 2*X_BYTES)     : x copies [stage]  (single copy per stage)
//   [+, 6*8)           : mbarriers [stage][warp]
#define SMEM_X_OFF    (2 * H_BYTES)
#define SMEM_MBAR_OFF (SMEM_X_OFF + 2 * X_BYTES)
#define SMEM_TOTAL    (SMEM_MBAR_OFF + 6 * 8)

__device__ __constant__ float kDampF = (float)(0.1 * 627.5094740631 /
                                               (0.529177210903 * 0.529177210903));

__device__ __forceinline__ uint32_t s2u(const void* p) {
    uint32_t a;
    asm("{ .reg .u64 t; cvta.to.shared.u64 t, %1; cvt.u32.u64 %0, t; }"
        : "=r"(a) : "l"(p));
    return a;
}

__device__ __forceinline__ void mbar_init(uint32_t mbar, uint32_t count) {
    asm volatile("mbarrier.init.shared.b64 [%0], %1;" :: "r"(mbar), "r"(count) : "memory");
}

__device__ __forceinline__ void mbar_expect_tx(uint32_t mbar, uint32_t bytes) {
    asm volatile("mbarrier.arrive.expect_tx.shared.b64 _, [%0], %1;"
                 :: "r"(mbar), "r"(bytes) : "memory");
}

__device__ __forceinline__ void mbar_wait(uint32_t mbar, uint32_t parity) {
    asm volatile(
        "{\n\t"
        ".reg .pred P;\n\t"
        "WAIT_%=:\n\t"
        "mbarrier.try_wait.parity.shared.b64 P, [%0], %1;\n\t"
        "@!P bra WAIT_%=;\n\t"
        "}"
        :: "r"(mbar), "r"(parity) : "memory");
}

__device__ __forceinline__ void bulk_g2s_ef(uint32_t dst_smem, const void* src_gmem,
                                            uint32_t bytes, uint32_t mbar) {
    asm volatile(
        "{\n\t"
        ".reg .b64 pol;\n\t"
        "createpolicy.fractional.L2::evict_first.b64 pol, 1.0;\n\t"
        "cp.async.bulk.shared::cluster.global.mbarrier::complete_tx::bytes.L2::cache_hint "
        "[%0], [%1], %2, [%3], pol;\n\t"
        "}"
        :: "r"(dst_smem), "l"(src_gmem), "r"(bytes), "r"(mbar) : "memory");
}

extern __shared__ char smem_raw[];

// issue stage st: three per-warp H thirds; x once, attached to warp0's barrier
__device__ __forceinline__ void issue_stage(uint32_t Hs_u, uint32_t xs_u, uint32_t mbar_base,
                                            int st, const float* hp, const float* xp) {
    const uint32_t hdst = Hs_u + (uint32_t)st * H_BYTES;
    const uint32_t mb   = mbar_base + (uint32_t)(st * 3) * 8u;
    // warp 0 third + the stage's single x copy
    mbar_expect_tx(mb, HW_BYTES + X_BYTES);
    bulk_g2s_ef(hdst, hp, HW_BYTES, mb);
    bulk_g2s_ef(xs_u + (uint32_t)st * X_BYTES, xp, X_BYTES, mb);
    // warps 1,2 thirds
    #pragma unroll
    for (int w = 1; w < 3; ++w) {
        mbar_expect_tx(mb + 8u * w, HW_BYTES);
        bulk_g2s_ef(hdst + (uint32_t)w * HW_BYTES, hp + w * (ROWS_W * D), HW_BYTES, mb + 8u * w);
    }
}

__global__ void __launch_bounds__(D, 3)
force_agg_kernel(const float* __restrict__ ns,
                 const float* __restrict__ hess,
                 float* __restrict__ out, int M) {
    float* Hs = reinterpret_cast<float*>(smem_raw);                 // [2][DD]
    float* xs = reinterpret_cast<float*>(smem_raw + SMEM_X_OFF);    // [2][D]
    const uint32_t mbar_base = s2u(smem_raw + SMEM_MBAR_OFF);       // [2][3]

    const int t = threadIdx.x;     // 0..95
    const int b = blockIdx.x;
    const int w = t >> 5;          // my warp = my third

    if (t < 6) mbar_init(mbar_base + 8u * t, 1);
    __syncthreads();

    // interleaved assignment: molecules b, b+456, ...
    const int stride = gridDim.x;
    const int cnt = (M - b + stride - 1) / stride;

    const uint32_t Hs_u = s2u(Hs);
    const uint32_t xs_u = s2u(xs);

    const size_t mstepH = (size_t)stride * DD;
    const size_t mstepX = (size_t)stride * D;
    const float* hess_p = hess + (size_t)b * DD;
    const float* ns_p   = ns   + (size_t)b * D;
    float* out_p        = out  + (size_t)b * D + t;

    // prologue: stage 0 for k=0
    if (t == 0) issue_stage(Hs_u, xs_u, mbar_base, 0, hess_p, ns_p);
    const float* hess_next = hess_p + mstepH;
    const float* ns_next   = ns_p   + mstepX;

    const int c0 = t % D4;         // rotated vec4-column start (conflict-free)
    const uint32_t my_mb_off = (uint32_t)w * 8u;

    for (int k = 0; k < cnt; ++k) {
        const int s = k & 1;
        const uint32_t mb_stage = mbar_base + (uint32_t)(s * 3) * 8u;
        const uint32_t parity = (uint32_t)((k >> 1) & 1);

        // prefetch k+1 into stage s^1 (freed by the sync ending iter k-1)
        if (t == 0 && (k + 1) < cnt)
            issue_stage(Hs_u, xs_u, mbar_base, s ^ 1, hess_next, ns_next);
        hess_next += mstepH;
        ns_next   += mstepX;

        // wait for my H third; non-zero warps also wait on warp0's barrier (x copy)
        mbar_wait(mb_stage + my_mb_off, parity);
        if (w != 0) mbar_wait(mb_stage, parity);

        // vectorized dot product: LDS.128 on H row and the shared x copy
        const float4* __restrict__ Hrow4 =
            reinterpret_cast<const float4*>(Hs + (size_t)s * DD + (size_t)t * D);
        const float* __restrict__ xvec = xs + s * D;
        const float4* __restrict__ xv4 = reinterpret_cast<const float4*>(xvec);

        float a0 = 0.f, a1 = 0.f, a2 = 0.f, a3 = 0.f;
        int c = c0;
        #pragma unroll
        for (int it = 0; it < D4; ++it) {
            float4 h = Hrow4[c];
            float4 xv = xv4[c];
            a0 = fmaf(h.x, xv.x, a0);
            a1 = fmaf(h.y, xv.y, a1);
            a2 = fmaf(h.z, xv.z, a2);
            a3 = fmaf(h.w, xv.w, a3);
            ++c;
            if (c == D4) c = 0;
        }
        const float acc = fmaf(kDampF, xvec[t], (a0 + a1) + (a2 + a3));

        *out_p = acc;
        out_p += mstepX;

        // stage s fully consumed before iter k+1 refills it
        __syncthreads();
    }
}

extern "C" void kernel_launch(void* const* d_in, const int* in_sizes, int n_in,
                              void* d_out, int out_size) {
    const float* ns   = (const float*)d_in[0];   // [N_tot,3] -> flat [M*96]
    const float* hess = (const float*)d_in[1];   // [M*96, 96]
    float* out = (float*)d_out;

    const int M = in_sizes[1] / DD;              // 8192

    cudaFuncSetAttribute(force_agg_kernel,
                         cudaFuncAttributeMaxDynamicSharedMemorySize, SMEM_TOTAL);
    force_agg_kernel<<<NBLOCKS, D, SMEM_TOTAL>>>(ns, hess, out, M);
}

// round 13
// speedup vs baseline: 1.0338x; 1.0150x over previous
#include <cuda_runtime.h>
#include <cstdint>
#include <cstddef>

// f = H @ x + damp * x per molecule.
// hess: [M*96, 96] f32 row-major, ns: flat [M*96] f32, out: flat [M*96] f32.
// FINAL converged config (best measured kernel time): 456 persistent CTAs
// (3/SM), 2-stage TMA ring, ONE mbarrier per stage, two bulk copies per
// molecule, L2 evict_first, LDS.128 rotated-column consumer.
// Pinned at measured ~6.4TB/s LTS ceiling: 308MB / 6.4TB/s = 48.1us floor.
#define D 96
#define D4 24                  // D/4 vec4 columns
#define DD (D * D)
#define H_BYTES (DD * 4)       // 36864
#define X_BYTES (D * 4)        // 384
#define NBLOCKS 456            // 152 SMs * 3 CTAs/SM (GB300)

// dynamic smem layout:
//   [0,            2*H_BYTES)              : H stages (2 x 36864)
//   [2*H_BYTES,    2*H_BYTES + 2*X_BYTES)  : x stages (2 x 384)
//   [...,          +16)                    : 2 mbarriers (8B each)
#define SMEM_X_OFF    (2 * H_BYTES)
#define SMEM_MBAR_OFF (2 * H_BYTES + 2 * X_BYTES)
#define SMEM_TOTAL    (SMEM_MBAR_OFF + 16)

__device__ __constant__ float kDampF = (float)(0.1 * 627.5094740631 /
                                               (0.529177210903 * 0.529177210903));

__device__ __forceinline__ uint32_t s2u(const void* p) {
    uint32_t a;
    asm("{ .reg .u64 t; cvta.to.shared.u64 t, %1; cvt.u32.u64 %0, t; }"
        : "=r"(a) : "l"(p));
    return a;
}

__device__ __forceinline__ void mbar_init(uint32_t mbar, uint32_t count) {
    asm volatile("mbarrier.init.shared.b64 [%0], %1;" :: "r"(mbar), "r"(count) : "memory");
}

__device__ __forceinline__ void mbar_expect_tx(uint32_t mbar, uint32_t bytes) {
    asm volatile("mbarrier.arrive.expect_tx.shared.b64 _, [%0], %1;"
                 :: "r"(mbar), "r"(bytes) : "memory");
}

__device__ __forceinline__ void mbar_wait(uint32_t mbar, uint32_t parity) {
    asm volatile(
        "{\n\t"
        ".reg .pred P;\n\t"
        "WAIT_%=:\n\t"
        "mbarrier.try_wait.parity.shared.b64 P, [%0], %1;\n\t"
        "@!P bra WAIT_%=;\n\t"
        "}"
        :: "r"(mbar), "r"(parity) : "memory");
}

// bulk G->S copy with L2 evict-first policy (zero-reuse 302MB stream)
__device__ __forceinline__ void bulk_g2s_ef(uint32_t dst_smem, const void* src_gmem,
                                            uint32_t bytes, uint32_t mbar) {
    asm volatile(
        "{\n\t"
        ".reg .b64 pol;\n\t"
        "createpolicy.fractional.L2::evict_first.b64 pol, 1.0;\n\t"
        "cp.async.bulk.shared::cluster.global.mbarrier::complete_tx::bytes.L2::cache_hint "
        "[%0], [%1], %2, [%3], pol;\n\t"
        "}"
        :: "r"(dst_smem), "l"(src_gmem), "r"(bytes), "r"(mbar) : "memory");
}

extern __shared__ char smem_raw[];

__global__ void __launch_bounds__(D, 3)
force_agg_kernel(const float* __restrict__ ns,
                 const float* __restrict__ hess,
                 float* __restrict__ out, int M) {
    float* Hs = reinterpret_cast<float*>(smem_raw);                 // [2][DD]
    float* xs = reinterpret_cast<float*>(smem_raw + SMEM_X_OFF);    // [2][D]
    const uint32_t mbar0 = s2u(smem_raw + SMEM_MBAR_OFF);
    const uint32_t mbar1 = mbar0 + 8;

    const int t = threadIdx.x;     // 0..95
    const int b = blockIdx.x;

    if (t == 0) {
        mbar_init(mbar0, 1);
        mbar_init(mbar1, 1);
    }
    __syncthreads();

    const int stride = gridDim.x;
    const int cnt = (M - b + stride - 1) / stride;

    const uint32_t Hs_u = s2u(Hs);
    const uint32_t xs_u = s2u(xs);

    // prologue: stage 0 for k=0
    if (t == 0) {
        mbar_expect_tx(mbar0, H_BYTES + X_BYTES);
        bulk_g2s_ef(Hs_u, hess + (size_t)b * DD, H_BYTES, mbar0);
        bulk_g2s_ef(xs_u, ns + (size_t)b * D, X_BYTES, mbar0);
    }

    uint32_t phase0 = 0, phase1 = 0;
    const int c0 = t % D4;         // rotated vec4-column start (conflict-free)

    const size_t mstepH = (size_t)stride * DD;
    const size_t mstepX = (size_t)stride * D;
    const float* hess_next = hess + (size_t)b * DD + mstepH;   // molecule k=1
    const float* ns_next   = ns   + (size_t)b * D  + mstepX;
    float* out_p           = out  + (size_t)b * D  + t;

    for (int k = 0; k < cnt; ++k) {
        const int s = k & 1;

        // prefetch k+1 into stage s^1 (freed by the sync ending iter k-1)
        if (t == 0 && (k + 1) < cnt) {
            const int s2 = s ^ 1;
            const uint32_t mbar_n = s2 ? mbar1 : mbar0;
            mbar_expect_tx(mbar_n, H_BYTES + X_BYTES);
            bulk_g2s_ef(Hs_u + (uint32_t)s2 * H_BYTES, hess_next, H_BYTES, mbar_n);
            bulk_g2s_ef(xs_u + (uint32_t)s2 * X_BYTES, ns_next, X_BYTES, mbar_n);
        }
        hess_next += mstepH;
        ns_next   += mstepX;

        // wait for stage s
        if (s) { mbar_wait(mbar1, phase1); phase1 ^= 1; }
        else   { mbar_wait(mbar0, phase0); phase0 ^= 1; }

        // vectorized dot product: LDS.128 on H row and x, rotated start.
        // 16B-group = (c mod 8): distinct within each 8-lane phase -> bank-free.
        const float4* __restrict__ Hrow4 =
            reinterpret_cast<const float4*>(Hs + (size_t)s * DD + (size_t)t * D);
        const float4* __restrict__ xv4 =
            reinterpret_cast<const float4*>(xs + s * D);

        float a0 = 0.f, a1 = 0.f, a2 = 0.f, a3 = 0.f;
        int c = c0;
        #pragma unroll
        for (int it = 0; it < D4; ++it) {
            float4 h = Hrow4[c];
            float4 xv = xv4[c];
            a0 = fmaf(h.x, xv.x, a0);
            a1 = fmaf(h.y, xv.y, a1);
            a2 = fmaf(h.z, xv.z, a2);
            a3 = fmaf(h.w, xv.w, a3);
            ++c;
            if (c == D4) c = 0;
        }
        const float x_t = (xs + s * D)[t];
        const float acc = fmaf(kDampF, x_t, (a0 + a1) + (a2 + a3));

        *out_p = acc;
        out_p += mstepX;

        // stage s fully consumed before iter k+1 refills it
        __syncthreads();
    }
}

extern "C" void kernel_launch(void* const* d_in, const int* in_sizes, int n_in,
                              void* d_out, int out_size) {
    const float* ns   = (const float*)d_in[0];   // [N_tot,3] -> flat [M*96]
    const float* hess = (const float*)d_in[1];   // [M*96, 96]
    float* out = (float*)d_out;

    const int M = in_sizes[1] / DD;              // 8192

    cudaFuncSetAttribute(force_agg_kernel,
                         cudaFuncAttributeMaxDynamicSharedMemorySize, SMEM_TOTAL);
    force_agg_kernel<<<NBLOCKS, D, SMEM_TOTAL>>>(ns, hess, out, M);
}